// round 17
// baseline (speedup 1.0000x reference)
#include <cuda_runtime.h>
#include <math.h>

// Problem constants (fixed by the dataset)
#define NN 10000   // nodes
#define PP 25000   // edge-pairs
#define BB 8       // batch
#define FF 16      // feats
#define MM 32      // MLP width
#define TWO_F (2*FF)          // 32
#define NODE_STRIDE (BB*FF)   // 128 floats per node
#define XELEMS (NN*NODE_STRIDE)

// intermediate node-state buffer (layer-0 output acts), [N][B][F]
__device__ __align__(16) float g_x1[XELEMS];

// ---------------------------------------------------------------------------
// f32x2 packed-math helpers (sm_103a)
__device__ __forceinline__ unsigned long long pk2(float x, float y) {
    unsigned long long r;
    asm("mov.b64 %0,{%1,%2};" : "=l"(r) : "f"(x), "f"(y));
    return r;
}
__device__ __forceinline__ void upk2(unsigned long long v, float& x, float& y) {
    asm("mov.b64 {%0,%1},%2;" : "=f"(x), "=f"(y) : "l"(v));
}
__device__ __forceinline__ unsigned long long fma2(unsigned long long a,
                                                   unsigned long long b,
                                                   unsigned long long c) {
    unsigned long long d;
    asm("fma.rn.f32x2 %0,%1,%2,%3;" : "=l"(d) : "l"(a), "l"(b), "l"(c));
    return d;
}
__device__ __forceinline__ float silu_f(float v) {
    return __fdividef(v, 1.0f + __expf(-v));
}
// cp.async 16B copy (global -> shared), bypassing registers
__device__ __forceinline__ void cpa16(float* dst_smem, const float* src) {
    unsigned saddr = (unsigned)__cvta_generic_to_shared(dst_smem);
    asm volatile("cp.async.cg.shared.global [%0], [%1], 16;" :: "r"(saddr), "l"(src));
}
#define CP_COMMIT() asm volatile("cp.async.commit_group;")
#define CP_WAIT(n)  asm volatile("cp.async.wait_group %0;" :: "n"(n))
// vectorized global reduction: one instruction, 4 floats
__device__ __forceinline__ void red_v4(float* p, float a, float b, float c, float d) {
    asm volatile("red.global.add.v4.f32 [%0], {%1,%2,%3,%4};"
                 :: "l"(p), "f"(a), "f"(b), "f"(c), "f"(d) : "memory");
}

// ---------------------------------------------------------------------------
// zero g_x1 and d_out (layer 0 reads h directly; no transpose needed)
__global__ void zero_kernel(float* __restrict__ out) {
    int idx = blockIdx.x * blockDim.x + threadIdx.x;
    if (idx >= XELEMS / 4) return;
    const float4 z = make_float4(0.f, 0.f, 0.f, 0.f);
    ((float4*)g_x1)[idx] = z;
    ((float4*)out)[idx]  = z;
}

// ---------------------------------------------------------------------------
// One warp per edge-pair. 2-stage cp.async weight ring + in-place k-major
// activations with column-pair lane mapping (R16). Output layer remapped to
// lane = (batch, feature-quad): Wout reads are LDS.128 broadcasts and the
// scatter is 2 x red.global.add.v4.f32 (128B contiguous for layer 0).
#define WPB 4  // 36.5KB smem + <=85 regs -> 6 blocks = 24 warps/SM

__device__ __forceinline__ void stage_issue(float* dst, const float* src,
                                            int lane, int nfloats) {
    #pragma unroll
    for (int i = lane * 4; i < nfloats; i += 128)
        cpa16(dst + i, src + i);
    CP_COMMIT();
}

// one MLP layer: [B,32] @ [32,32] + bias(reg) + silu; in-place activations.
// lane covers columns (2i, 2i+1), batches 4h..4h+3  (i = lane&15, h = lane>>4)
__device__ __forceinline__ void mlp32_layer_ip(const float* __restrict__ Wsm,
                                               float2 bv2,
                                               float (*X)[BB], int lane)
{
    const int i = lane & 15;
    const int h = lane >> 4;
    unsigned long long acc2[4];
    acc2[0] = acc2[1] = pk2(bv2.x, bv2.x);   // col 2i
    acc2[2] = acc2[3] = pk2(bv2.y, bv2.y);   // col 2i+1
    #pragma unroll
    for (int k = 0; k < MM; k++) {
        const float2 wp = *(const float2*)&Wsm[k * MM + 2 * i];   // 1 wavefront
        const unsigned long long w2a = pk2(wp.x, wp.x);
        const unsigned long long w2b = pk2(wp.y, wp.y);
        const ulonglong2 r = *(const ulonglong2*)&X[k][4 * h];    // 1 wavefront
        acc2[0] = fma2(r.x, w2a, acc2[0]);
        acc2[1] = fma2(r.y, w2a, acc2[1]);
        acc2[2] = fma2(r.x, w2b, acc2[2]);
        acc2[3] = fma2(r.y, w2b, acc2[3]);
    }
    __syncwarp();   // all lanes finished reading X before anyone overwrites it
    float s[8];
    #pragma unroll
    for (int j = 0; j < 4; j++) {
        float a, b;
        upk2(acc2[j], a, b);
        s[2 * j]     = silu_f(a);
        s[2 * j + 1] = silu_f(b);
    }
    *(float4*)&X[2 * i][4 * h]     = make_float4(s[0], s[1], s[2], s[3]);
    *(float4*)&X[2 * i + 1][4 * h] = make_float4(s[4], s[5], s[6], s[7]);
    __syncwarp();
}

template<int SNI, int SBI, int SNO, int SBO>
__global__ void __launch_bounds__(WPB * 32, 6)
edge_kernel(const float* __restrict__ Wi0,  const float* __restrict__ Wih,
            const float* __restrict__ Wiout,const float* __restrict__ bi0,
            const float* __restrict__ bih,  const float* __restrict__ biout,
            const float* __restrict__ Wf0,  const float* __restrict__ Wfh,
            const float* __restrict__ Wfout,const float* __restrict__ bf0,
            const float* __restrict__ bfh,  const float* __restrict__ bfout,
            const int* __restrict__ src,    const int* __restrict__ dst,
            const float* __restrict__ xcur, float* __restrict__ ybase)
{
    // per-warp: 2-stage weight ring (4KB each) + in-place k-major acts (1KB)
    __shared__ __align__(16) float wst[WPB][2][MM * MM];
    __shared__ __align__(16) float smX[WPB][MM][BB];

    const int w    = threadIdx.x >> 5;
    const int lane = threadIdx.x & 31;
    const int e    = blockIdx.x * WPB + w;
    if (e > PP) return;

    const bool fx   = (e == PP);
    const int  eidx = fx ? 2 * PP : e;   // fixed edge is the last entry
    const int  d = dst[eidx];
    const int  s = src[eidx];

    const int Pp = fx ? 1 : PP;
    const int pe = fx ? 0 : e;

    const float* W0   = (fx ? Wf0   : Wi0)   + (size_t)pe * (TWO_F * MM);
    const float* b0   = (fx ? bf0   : bi0)   + (size_t)pe * MM;
    const float* Wout = (fx ? Wfout : Wiout) + (size_t)pe * (MM * FF);
    const float* bout = (fx ? bfout : biout) + (size_t)pe * FF;
    const float* WhB  = fx ? Wfh : Wih;
    const float* bhB  = fx ? bfh : bih;
    const float* Wh0  = WhB + (size_t)pe * (MM * MM);
    const float* Wh1  = WhB + ((size_t)Pp + pe) * (MM * MM);
    const float* bh0  = bhB + (size_t)pe * MM;
    const float* bh1  = bhB + ((size_t)Pp + pe) * MM;

    float* st0 = &wst[w][0][0];
    float* st1 = &wst[w][1][0];
    float (*X)[BB] = smX[w];

    // prefetch layer0 + hidden0 weights immediately (groups g0, g1)
    stage_issue(st0, W0,  lane, MM * MM);
    stage_issue(st1, Wh0, lane, MM * MM);

    // preload all biases (latency hidden behind the cp.async ramp + gather)
    const int ip = lane & 15;
    const float2 bv0  = *(const float2*)&b0[2 * ip];
    const float2 bvh0 = *(const float2*)&bh0[2 * ip];
    const float2 bvh1 = *(const float2*)&bh1[2 * ip];
    const int   fq   = (lane & 3) * 4;          // out-layer feature quad
    const float4 ob4 = *(const float4*)&bout[fq];

    // ---- gather edge input into k-major smem (overlaps with prefetch)
    {
        const float* xd = xcur + (size_t)d * SNI;
        const float* xs = xcur + (size_t)s * SNI;
        const float* xg = (lane < FF) ? xd : xs;
        const int f0 = lane & 15;
        float v[BB];
        #pragma unroll
        for (int b = 0; b < BB; b++) v[b] = xg[(size_t)b * SBI + f0];
        *(float4*)&X[lane][0] = make_float4(v[0], v[1], v[2], v[3]);
        *(float4*)&X[lane][4] = make_float4(v[4], v[5], v[6], v[7]);
    }
    __syncwarp();

    // ---- layer 0 (st0; hidden0 streaming into st1 behind it)
    CP_WAIT(1); __syncwarp();
    mlp32_layer_ip(st0, bv0, X, lane);
    stage_issue(st0, Wh1, lane, MM * MM);   // g2

    // ---- hidden 0 (st1)
    CP_WAIT(1); __syncwarp();
    mlp32_layer_ip(st1, bvh0, X, lane);
    stage_issue(st1, Wout, lane, MM * FF);  // g3 (2KB)

    // ---- hidden 1 (st0)
    CP_WAIT(1); __syncwarp();
    mlp32_layer_ip(st0, bvh1, X, lane);

    // ---- output layer: [B,32] @ [32,16] from st1
    // lane owns batch b = lane>>2 and feature quad fq = (lane&3)*4:
    // Wout read = per-lane LDS.128 (64B/warp broadcast), act = 4B row read.
    CP_WAIT(0); __syncwarp();
    const int b = lane >> 2;
    unsigned long long o01 = pk2(ob4.x, ob4.y);
    unsigned long long o23 = pk2(ob4.z, ob4.w);
    #pragma unroll
    for (int k = 0; k < MM; k++) {
        const float4 w4 = *(const float4*)&st1[k * FF + fq];
        const float a = X[k][b];
        const unsigned long long a2 = pk2(a, a);
        o01 = fma2(pk2(w4.x, w4.y), a2, o01);
        o23 = fma2(pk2(w4.z, w4.w), a2, o23);
    }
    float o0, o1, o2, o3;
    upk2(o01, o0, o1);
    upk2(o23, o2, o3);

    // ---- scatter: one red.v4 per target (layer0: 128B contiguous per warp)
    red_v4(ybase + (size_t)d * SNO + (size_t)b * SBO + fq, o0, o1, o2, o3);
    if (!fx)
        red_v4(ybase + (size_t)s * SNO + (size_t)b * SBO + fq, -o0, -o1, -o2, -o3);
}

// ---------------------------------------------------------------------------
extern "C" void kernel_launch(void* const* d_in, const int* in_sizes, int n_in,
                              void* d_out, int out_size) {
    const float* h     = (const float*)d_in[0];
    const float* Wi0   = (const float*)d_in[1];
    const float* Wih   = (const float*)d_in[2];
    const float* Wiout = (const float*)d_in[3];
    const float* bi0   = (const float*)d_in[4];
    const float* bih   = (const float*)d_in[5];
    const float* biout = (const float*)d_in[6];
    const float* Wf0   = (const float*)d_in[7];
    const float* Wfh   = (const float*)d_in[8];
    const float* Wfout = (const float*)d_in[9];
    const float* bf0   = (const float*)d_in[10];
    const float* bfh   = (const float*)d_in[11];
    const float* bfout = (const float*)d_in[12];
    const int*   src   = (const int*)d_in[13];
    const int*   dst   = (const int*)d_in[14];
    float*       out   = (float*)d_out;

    const int tb = 256;
    const int zblocks = (XELEMS / 4 + tb - 1) / tb;
    const int eblocks = (PP + 1 + WPB - 1) / WPB;

    float* x1 = nullptr;
    cudaGetSymbolAddress((void**)&x1, g_x1);   // host-side address query only

    zero_kernel<<<zblocks, tb>>>(out);

    // layer 0: h [B][N][F] -> g_x1 [N][B][F]
    edge_kernel<FF, NN * FF, NODE_STRIDE, FF><<<eblocks, WPB * 32>>>(
        Wi0, Wih, Wiout, bi0, bih, biout,
        Wf0, Wfh, Wfout, bf0, bfh, bfout,
        src, dst, h, x1);

    // layer 1: g_x1 [N][B][F] -> d_out [B][N][F] (transpose folded in)
    edge_kernel<NODE_STRIDE, FF, FF, NN * FF><<<eblocks, WPB * 32>>>(
        Wi0   + (size_t)PP * TWO_F * MM,
        Wih   + (size_t)2 * PP * MM * MM,
        Wiout + (size_t)PP * MM * FF,
        bi0   + (size_t)PP * MM,
        bih   + (size_t)2 * PP * MM,
        biout + (size_t)PP * FF,
        Wf0   + (size_t)TWO_F * MM,
        Wfh   + (size_t)2 * MM * MM,
        Wfout + (size_t)MM * FF,
        bf0   + (size_t)MM,
        bfh   + (size_t)2 * MM,
        bfout + (size_t)FF,
        src, dst, x1, out);
}